// round 4
// baseline (speedup 1.0000x reference)
#include <cuda_runtime.h>
#include <cuda_bf16.h>
#include <math_constants.h>
#include <cstdint>

#define LL 768
#define HH 8
#define EE 64
#define NH 32
#define DD 192
#define BQ 64
#define NTILE 12
#define KSTR 200   // padded smem row stride (bf16): 400B ≡ 16B mod 128 -> conflict-free ldmatrix
#define VSTR 72    // 144B ≡ 16B mod 128 -> conflict-free

// ---------------- scratch (device globals; no allocs) ----------------
__device__ __nv_bfloat16 g_Qhi[(size_t)NH * LL * DD];
__device__ __nv_bfloat16 g_Qlo[(size_t)NH * LL * DD];
__device__ __nv_bfloat16 g_Khi[(size_t)NH * LL * DD];
__device__ __nv_bfloat16 g_Klo[(size_t)NH * LL * DD];
__device__ __nv_bfloat16 g_Vhi[(size_t)NH * EE * LL];   // transposed [nh][e][s]
__device__ __nv_bfloat16 g_Vlo[(size_t)NH * EE * LL];

// m16n8k16 row.col bf16 MMA, f32 accumulate
__device__ __forceinline__ void mma_bf16(float* c, const uint32_t* a, uint32_t b0, uint32_t b1) {
    asm volatile("mma.sync.aligned.m16n8k16.row.col.f32.bf16.bf16.f32 "
                 "{%0,%1,%2,%3}, {%4,%5,%6,%7}, {%8,%9}, {%0,%1,%2,%3};"
                 : "+f"(c[0]), "+f"(c[1]), "+f"(c[2]), "+f"(c[3])
                 : "r"(a[0]), "r"(a[1]), "r"(a[2]), "r"(a[3]), "r"(b0), "r"(b1));
}

// ldmatrix x4: 4x (8x8 b16) tiles; lane L addresses row L&7 of tile L>>3
__device__ __forceinline__ void ldm_x4(uint32_t* r, uint32_t saddr) {
    asm volatile("ldmatrix.sync.aligned.m8n8.x4.shared.b16 {%0,%1,%2,%3}, [%4];"
                 : "=r"(r[0]), "=r"(r[1]), "=r"(r[2]), "=r"(r[3]) : "r"(saddr));
}

__device__ __forceinline__ uint32_t smem_u32(const void* p) {
    uint32_t a;
    asm("{ .reg .u64 t; cvta.to.shared.u64 t, %1; cvt.u32.u64 %0, t; }" : "=r"(a) : "l"(p));
    return a;
}

__device__ __forceinline__ uint32_t pack_hi(float x, float y, uint32_t& lo) {
    __nv_bfloat162 h2;
    h2.x = __float2bfloat16(x);
    h2.y = __float2bfloat16(y);
    __nv_bfloat162 l2;
    l2.x = __float2bfloat16(x - __bfloat162float(h2.x));
    l2.y = __float2bfloat16(y - __bfloat162float(h2.y));
    lo = *(uint32_t*)&l2;
    return *(uint32_t*)&h2;
}

// ---------------------------------------------------------------------------
// prep_qk: augmented Q'/K' (d=192) as bf16 hi/lo, row-major [nh][l][192].
// Fast intrinsics (MUFU) — phase error ~1e-5 absolute, well under tolerance.
// ---------------------------------------------------------------------------
__global__ void prep_qk(const float* __restrict__ q, const float* __restrict__ k,
                        const float* __restrict__ freqs, const float* __restrict__ offsets,
                        const float* __restrict__ gains, const float* __restrict__ gate) {
    int e  = threadIdx.x & 63;
    int l  = blockIdx.x * 4 + (threadIdx.x >> 6);
    int nh = blockIdx.y;
    int n = nh >> 3, h = nh & 7;
    int he = h * 64 + e;

    float fr  = freqs[he];
    float f   = 0.5f / (1.0f + __expf(-fr));
    float off = offsets[he];
    float gn  = gains[he];
    float g   = (gn > 8.0f) ? gn : __logf(1.0f + __expf(gn));
    float gt  = gate[he];
    float c   = (1.0f - gt) * g * g;

    float lf    = (float)l;
    float fl    = f * lf;
    float resid = fmaf(f, lf, -fl);              // exact low part of f*l
    float frac  = (fl - floorf(fl)) + resid;     // fractional turns, high accuracy
    float phk   = 6.28318530717958647692f * frac;
    float argq  = phk + off;
    float cq = __cosf(argq), sq = __sinf(argq);
    float ck = __cosf(phk),  sk = __sinf(phk);

    size_t qi = ((size_t)(n * LL + l) * HH + h) * EE + e;
    float qv = q[qi] * 0.125f;            // softmax temp folded into Q'
    float kv = k[qi];

    float qs[3] = { qv * gt, qv * c * cq, qv * c * sq };
    float ks[3] = { kv,      kv * ck,     kv * sk     };

    size_t base = ((size_t)nh * LL + l) * DD;
    #pragma unroll
    for (int kk = 0; kk < 3; kk++) {
        float v = qs[kk];
        __nv_bfloat16 hi = __float2bfloat16(v);
        g_Qhi[base + kk * 64 + e] = hi;
        g_Qlo[base + kk * 64 + e] = __float2bfloat16(v - __bfloat162float(hi));
        float w = ks[kk];
        __nv_bfloat16 whi = __float2bfloat16(w);
        g_Khi[base + kk * 64 + e] = whi;
        g_Klo[base + kk * 64 + e] = __float2bfloat16(w - __bfloat162float(whi));
    }
}

// ---------------------------------------------------------------------------
// prep_v: V transposed to [nh][e][s] bf16 hi/lo (s contiguous).
// ---------------------------------------------------------------------------
__global__ void prep_v(const float* __restrict__ values) {
    __shared__ float sm[64 * 65];
    int t = blockIdx.x, nh = blockIdx.y;
    int n = nh >> 3, h = nh & 7;
    int s0 = t * 64;

    #pragma unroll
    for (int i = 0; i < 16; i++) {
        int idx = threadIdx.x + i * 256;
        int r = idx >> 6, e = idx & 63;
        sm[e * 65 + r] = values[((size_t)(n * LL + s0 + r) * HH + h) * EE + e];
    }
    __syncthreads();

    #pragma unroll
    for (int i = 0; i < 8; i++) {
        int pid = threadIdx.x + i * 256;
        int e = pid >> 5, s2 = pid & 31;
        float v0 = sm[e * 65 + 2 * s2];
        float v1 = sm[e * 65 + 2 * s2 + 1];
        __nv_bfloat162 hi2, lo2;
        hi2.x = __float2bfloat16(v0);
        hi2.y = __float2bfloat16(v1);
        lo2.x = __float2bfloat16(v0 - __bfloat162float(hi2.x));
        lo2.y = __float2bfloat16(v1 - __bfloat162float(hi2.y));
        size_t o = ((size_t)nh * EE + e) * LL + s0 + 2 * s2;
        *(uint32_t*)(g_Vhi + o) = *(uint32_t*)&hi2;
        *(uint32_t*)(g_Vlo + o) = *(uint32_t*)&lo2;
    }
}

// ---------------------------------------------------------------------------
// attn: flash attention on HMMA (bf16 3-product split), ldmatrix B-frags.
// Block = 4 warps = 64 q-rows (warp owns 16). 12 s-tiles of 64.
// ---------------------------------------------------------------------------
__global__ __launch_bounds__(128)
void attn_kernel(const float* __restrict__ mask, const float* __restrict__ keylen,
                 float* __restrict__ out) {
    extern __shared__ __nv_bfloat16 smem[];
    __nv_bfloat16* sKhi = smem;                      // [64][KSTR]
    __nv_bfloat16* sKlo = smem + 64 * KSTR;
    __nv_bfloat16* sVhi = smem + 2 * 64 * KSTR;      // [64][VSTR]
    __nv_bfloat16* sVlo = smem + 2 * 64 * KSTR + 64 * VSTR;

    const int tid  = threadIdx.x;
    const int w    = tid >> 5;
    const int lane = tid & 31;
    const int g    = lane >> 2, t = lane & 3;
    const int nh   = blockIdx.y;
    const int nb   = nh >> 3, h = nh & 7;
    const int l0   = blockIdx.x * BQ;
    const int row0 = l0 + w * 16 + g;

    // ldmatrix lane addressing: tile j = lane>>3; row-within = lane&7
    const int rowoff = ((lane >> 4) << 3) + (lane & 7);   // 0-7 / 8-15 row of n-pair
    const int k8off  = ((lane >> 3) & 1) * 8;             // k+8 for tiles 1,3
    const uint32_t uKhi = smem_u32(sKhi) + (uint32_t)(rowoff * KSTR + k8off) * 2u;
    const uint32_t uKlo = smem_u32(sKlo) + (uint32_t)(rowoff * KSTR + k8off) * 2u;
    const uint32_t uVhi = smem_u32(sVhi) + (uint32_t)(rowoff * VSTR + k8off) * 2u;
    const uint32_t uVlo = smem_u32(sVlo) + (uint32_t)(rowoff * VSTR + k8off) * 2u;

    // ---- Q fragments, register resident (reused for all 12 s-tiles) ----
    uint32_t aQh[12][4], aQl[12][4];
    {
        const __nv_bfloat16* qh = g_Qhi + ((size_t)nh * LL + row0) * DD;
        const __nv_bfloat16* ql = g_Qlo + ((size_t)nh * LL + row0) * DD;
        #pragma unroll
        for (int c = 0; c < 12; c++) {
            int d0 = c * 16 + 2 * t;
            aQh[c][0] = *(const uint32_t*)(qh + d0);
            aQh[c][1] = *(const uint32_t*)(qh + 8 * DD + d0);
            aQh[c][2] = *(const uint32_t*)(qh + d0 + 8);
            aQh[c][3] = *(const uint32_t*)(qh + 8 * DD + d0 + 8);
            aQl[c][0] = *(const uint32_t*)(ql + d0);
            aQl[c][1] = *(const uint32_t*)(ql + 8 * DD + d0);
            aQl[c][2] = *(const uint32_t*)(ql + d0 + 8);
            aQl[c][3] = *(const uint32_t*)(ql + 8 * DD + d0 + 8);
        }
    }

    float O[8][4];
    #pragma unroll
    for (int n = 0; n < 8; n++)
        #pragma unroll
        for (int j = 0; j < 4; j++) O[n][j] = 0.f;
    float m0 = -CUDART_INF_F, m1 = -CUDART_INF_F, ls0 = 0.f, ls1 = 0.f;

    const float* mrow0b = mask + (size_t)row0 * LL;
    const float* mrow1b = mrow0b + 8 * LL;
    const float* klb    = keylen + (size_t)nb * LL;

    for (int it = 0; it < NTILE; it++) {
        __syncthreads();
        // ---- cooperative tile fill (row-major -> padded smem) ----
        {
            const uint4* sH = (const uint4*)(g_Khi + ((size_t)nh * LL + it * 64) * DD);
            const uint4* sL = (const uint4*)(g_Klo + ((size_t)nh * LL + it * 64) * DD);
            #pragma unroll
            for (int i = 0; i < 12; i++) {
                int idx = tid + i * 128;
                int r = idx / 24, c = idx % 24;
                *(uint4*)(sKhi + r * KSTR + c * 8) = sH[idx];
                *(uint4*)(sKlo + r * KSTR + c * 8) = sL[idx];
            }
            #pragma unroll
            for (int i = 0; i < 4; i++) {
                int idx = tid + i * 128;
                int r = idx / 8, c = idx % 8;
                size_t go = ((size_t)nh * EE + r) * LL + it * 64 + c * 8;
                *(uint4*)(sVhi + r * VSTR + c * 8) = *(const uint4*)(g_Vhi + go);
                *(uint4*)(sVlo + r * VSTR + c * 8) = *(const uint4*)(g_Vlo + go);
            }
        }
        __syncthreads();

        // ---- S = Q' K'^T : 12 k-chunks x 4 n-pairs x 3 products ----
        float S[8][4];
        #pragma unroll
        for (int n = 0; n < 8; n++)
            #pragma unroll
            for (int j = 0; j < 4; j++) S[n][j] = 0.f;

        #pragma unroll
        for (int c = 0; c < 12; c++) {
            #pragma unroll
            for (int np = 0; np < 4; np++) {
                uint32_t bh[4], bl[4];
                uint32_t off = (uint32_t)(np * 16 * KSTR * 2 + c * 32);
                ldm_x4(bh, uKhi + off);
                ldm_x4(bl, uKlo + off);
                mma_bf16(S[2*np],   aQh[c], bh[0], bh[1]);
                mma_bf16(S[2*np],   aQh[c], bl[0], bl[1]);
                mma_bf16(S[2*np],   aQl[c], bh[0], bh[1]);
                mma_bf16(S[2*np+1], aQh[c], bh[2], bh[3]);
                mma_bf16(S[2*np+1], aQh[c], bl[2], bl[3]);
                mma_bf16(S[2*np+1], aQl[c], bh[2], bh[3]);
            }
        }

        // ---- bias: 0.125 * (mask + keylen) ----
        {
            const float* mr0 = mrow0b + it * 64;
            const float* mr1 = mrow1b + it * 64;
            const float* kl  = klb + it * 64;
            #pragma unroll
            for (int n = 0; n < 8; n++) {
                int sc = n * 8 + 2 * t;
                float2 a0 = *(const float2*)(mr0 + sc);
                float2 a1 = *(const float2*)(mr1 + sc);
                float2 kk = *(const float2*)(kl + sc);
                S[n][0] += 0.125f * (a0.x + kk.x);
                S[n][1] += 0.125f * (a0.y + kk.y);
                S[n][2] += 0.125f * (a1.x + kk.x);
                S[n][3] += 0.125f * (a1.y + kk.y);
            }
        }

        // ---- online softmax (rows quad-local) ----
        float mx0 = S[0][0], mx1 = S[0][2];
        #pragma unroll
        for (int n = 0; n < 8; n++) {
            mx0 = fmaxf(mx0, fmaxf(S[n][0], S[n][1]));
            mx1 = fmaxf(mx1, fmaxf(S[n][2], S[n][3]));
        }
        mx0 = fmaxf(mx0, __shfl_xor_sync(0xffffffffu, mx0, 1));
        mx0 = fmaxf(mx0, __shfl_xor_sync(0xffffffffu, mx0, 2));
        mx1 = fmaxf(mx1, __shfl_xor_sync(0xffffffffu, mx1, 1));
        mx1 = fmaxf(mx1, __shfl_xor_sync(0xffffffffu, mx1, 2));
        float m0n = fmaxf(m0, mx0), m1n = fmaxf(m1, mx1);
        float c0 = __expf(m0 - m0n), c1 = __expf(m1 - m1n);
        m0 = m0n; m1 = m1n;
        float s0 = 0.f, s1 = 0.f;
        #pragma unroll
        for (int n = 0; n < 8; n++) {
            S[n][0] = __expf(S[n][0] - m0n);
            S[n][1] = __expf(S[n][1] - m0n);
            S[n][2] = __expf(S[n][2] - m1n);
            S[n][3] = __expf(S[n][3] - m1n);
            s0 += S[n][0] + S[n][1];
            s1 += S[n][2] + S[n][3];
            O[n][0] *= c0; O[n][1] *= c0;
            O[n][2] *= c1; O[n][3] *= c1;
        }
        s0 += __shfl_xor_sync(0xffffffffu, s0, 1);
        s0 += __shfl_xor_sync(0xffffffffu, s0, 2);
        s1 += __shfl_xor_sync(0xffffffffu, s1, 1);
        s1 += __shfl_xor_sync(0xffffffffu, s1, 2);
        ls0 = ls0 * c0 + s0;
        ls1 = ls1 * c1 + s1;

        // ---- P -> bf16 hi/lo A-fragments (in-register) ----
        uint32_t ph[4][4], pl[4][4];
        #pragma unroll
        for (int kc = 0; kc < 4; kc++) {
            ph[kc][0] = pack_hi(S[2*kc][0],   S[2*kc][1],   pl[kc][0]);
            ph[kc][1] = pack_hi(S[2*kc][2],   S[2*kc][3],   pl[kc][1]);
            ph[kc][2] = pack_hi(S[2*kc+1][0], S[2*kc+1][1], pl[kc][2]);
            ph[kc][3] = pack_hi(S[2*kc+1][2], S[2*kc+1][3], pl[kc][3]);
        }

        // ---- O += P V : 4 s-chunks x 4 e-pairs x 3 products ----
        #pragma unroll
        for (int kc = 0; kc < 4; kc++) {
            #pragma unroll
            for (int np = 0; np < 4; np++) {
                uint32_t vh[4], vl[4];
                uint32_t off = (uint32_t)(np * 16 * VSTR * 2 + kc * 32);
                ldm_x4(vh, uVhi + off);
                ldm_x4(vl, uVlo + off);
                mma_bf16(O[2*np],   ph[kc], vh[0], vh[1]);
                mma_bf16(O[2*np],   ph[kc], vl[0], vl[1]);
                mma_bf16(O[2*np],   pl[kc], vh[0], vh[1]);
                mma_bf16(O[2*np+1], ph[kc], vh[2], vh[3]);
                mma_bf16(O[2*np+1], ph[kc], vl[2], vl[3]);
                mma_bf16(O[2*np+1], pl[kc], vh[2], vh[3]);
            }
        }
    }

    // ---- epilogue ----
    float inv0 = 1.0f / ls0, inv1 = 1.0f / ls1;
    float* o0 = out + ((size_t)(nb * LL + row0) * HH + h) * EE;
    float* o1 = o0 + 8 * HH * EE;
    #pragma unroll
    for (int n = 0; n < 8; n++) {
        int e = n * 8 + 2 * t;
        *(float2*)(o0 + e) = make_float2(O[n][0] * inv0, O[n][1] * inv0);
        *(float2*)(o1 + e) = make_float2(O[n][2] * inv1, O[n][3] * inv1);
    }
}

// ---------------------------------------------------------------------------
extern "C" void kernel_launch(void* const* d_in, const int* in_sizes, int n_in,
                              void* d_out, int out_size) {
    const float* queries = (const float*)d_in[0];
    const float* keys    = (const float*)d_in[1];
    const float* values  = (const float*)d_in[2];
    const float* mask    = (const float*)d_in[3];
    const float* keylen  = (const float*)d_in[4];
    const float* freqs   = (const float*)d_in[5];
    const float* offsets = (const float*)d_in[6];
    const float* gains   = (const float*)d_in[7];
    const float* gate    = (const float*)d_in[8];
    float* out = (float*)d_out;

    prep_qk<<<dim3(LL / 4, NH), 256>>>(queries, keys, freqs, offsets, gains, gate);
    prep_v<<<dim3(NTILE, NH), 256>>>(values);

    const int smem = (2 * 64 * KSTR + 2 * 64 * VSTR) * 2;  // 69632 B
    cudaFuncSetAttribute(attn_kernel, cudaFuncAttributeMaxDynamicSharedMemorySize, smem);
    attn_kernel<<<dim3(LL / BQ, NH), 128, smem>>>(mask, keylen, out);
}

// round 5
// speedup vs baseline: 1.2640x; 1.2640x over previous
#include <cuda_runtime.h>
#include <cuda_bf16.h>
#include <math_constants.h>
#include <cstdint>

#define LL 768
#define HH 8
#define EE 64
#define NH 32
#define DD 192
#define BQ 64
#define NTILE 12
#define KSTR 200   // padded smem row stride (bf16)
#define VSTR 72

// ---------------- scratch (device globals; no allocs) ----------------
__device__ __nv_bfloat16 g_Qhi[(size_t)NH * LL * DD];
__device__ __nv_bfloat16 g_Qlo[(size_t)NH * LL * DD];
__device__ __nv_bfloat16 g_Khi[(size_t)NH * LL * DD];
__device__ __nv_bfloat16 g_Klo[(size_t)NH * LL * DD];
__device__ __nv_bfloat16 g_Vhi[(size_t)NH * EE * LL];   // transposed [nh][e][s]
__device__ __nv_bfloat16 g_Vlo[(size_t)NH * EE * LL];

// m16n8k16 row.col bf16 MMA, f32 accumulate
__device__ __forceinline__ void mma_bf16(float* c, const uint32_t* a, uint32_t b0, uint32_t b1) {
    asm volatile("mma.sync.aligned.m16n8k16.row.col.f32.bf16.bf16.f32 "
                 "{%0,%1,%2,%3}, {%4,%5,%6,%7}, {%8,%9}, {%0,%1,%2,%3};"
                 : "+f"(c[0]), "+f"(c[1]), "+f"(c[2]), "+f"(c[3])
                 : "r"(a[0]), "r"(a[1]), "r"(a[2]), "r"(a[3]), "r"(b0), "r"(b1));
}

__device__ __forceinline__ uint32_t smem_u32(const void* p) {
    uint32_t a;
    asm("{ .reg .u64 t; cvta.to.shared.u64 t, %1; cvt.u32.u64 %0, t; }" : "=r"(a) : "l"(p));
    return a;
}

#define CP16(dst, src) asm volatile("cp.async.cg.shared.global [%0], [%1], 16;" :: "r"(dst), "l"(src))
#define CP_COMMIT()    asm volatile("cp.async.commit_group;" ::: "memory")
#define CP_WAIT0()     asm volatile("cp.async.wait_group 0;" ::: "memory")

__device__ __forceinline__ uint32_t pack_hi(float x, float y, uint32_t& lo) {
    __nv_bfloat162 h2;
    h2.x = __float2bfloat16(x);
    h2.y = __float2bfloat16(y);
    __nv_bfloat162 l2;
    l2.x = __float2bfloat16(x - __bfloat162float(h2.x));
    l2.y = __float2bfloat16(y - __bfloat162float(h2.y));
    lo = *(uint32_t*)&l2;
    return *(uint32_t*)&h2;
}

// ---------------------------------------------------------------------------
// prep_qk: augmented Q'/K' (d=192) bf16 hi/lo. Params hoisted; 4 l per thread.
// ---------------------------------------------------------------------------
__global__ void prep_qk(const float* __restrict__ q, const float* __restrict__ k,
                        const float* __restrict__ freqs, const float* __restrict__ offsets,
                        const float* __restrict__ gains, const float* __restrict__ gate) {
    int e  = threadIdx.x & 63;
    int j  = threadIdx.x >> 6;               // 0..3
    int l0 = blockIdx.x * 16 + j * 4;        // grid.x = 48
    int nh = blockIdx.y;
    int n = nh >> 3, h = nh & 7;
    int he = h * 64 + e;

    float fr  = freqs[he];
    float f   = 0.5f / (1.0f + __expf(-fr));
    float off = offsets[he];
    float gn  = gains[he];
    float g   = (gn > 8.0f) ? gn : __logf(1.0f + __expf(gn));
    float gt  = gate[he];
    float c   = (1.0f - gt) * g * g;

    #pragma unroll
    for (int dl = 0; dl < 4; dl++) {
        int l = l0 + dl;
        float lf    = (float)l;
        float fl    = f * lf;
        float resid = fmaf(f, lf, -fl);
        float frac  = (fl - floorf(fl)) + resid;
        float phk   = 6.28318530717958647692f * frac;
        float argq  = phk + off;
        float cq = __cosf(argq), sq = __sinf(argq);
        float ck = __cosf(phk),  sk = __sinf(phk);

        size_t qi = ((size_t)(n * LL + l) * HH + h) * EE + e;
        float qv = q[qi] * 0.125f;
        float kv = k[qi];

        float qs[3] = { qv * gt, qv * c * cq, qv * c * sq };
        float ks[3] = { kv,      kv * ck,     kv * sk     };

        size_t base = ((size_t)nh * LL + l) * DD;
        #pragma unroll
        for (int kk = 0; kk < 3; kk++) {
            float v = qs[kk];
            __nv_bfloat16 hi = __float2bfloat16(v);
            g_Qhi[base + kk * 64 + e] = hi;
            g_Qlo[base + kk * 64 + e] = __float2bfloat16(v - __bfloat162float(hi));
            float w = ks[kk];
            __nv_bfloat16 whi = __float2bfloat16(w);
            g_Khi[base + kk * 64 + e] = whi;
            g_Klo[base + kk * 64 + e] = __float2bfloat16(w - __bfloat162float(whi));
        }
    }
}

// ---------------------------------------------------------------------------
// prep_v: V transposed to [nh][e][s] bf16 hi/lo (s contiguous).
// ---------------------------------------------------------------------------
__global__ void prep_v(const float* __restrict__ values) {
    __shared__ float sm[64 * 65];
    int t = blockIdx.x, nh = blockIdx.y;
    int n = nh >> 3, h = nh & 7;
    int s0 = t * 64;

    #pragma unroll
    for (int i = 0; i < 16; i++) {
        int idx = threadIdx.x + i * 256;
        int r = idx >> 6, e = idx & 63;
        sm[e * 65 + r] = values[((size_t)(n * LL + s0 + r) * HH + h) * EE + e];
    }
    __syncthreads();

    #pragma unroll
    for (int i = 0; i < 8; i++) {
        int pid = threadIdx.x + i * 256;
        int e = pid >> 5, s2 = pid & 31;
        float v0 = sm[e * 65 + 2 * s2];
        float v1 = sm[e * 65 + 2 * s2 + 1];
        __nv_bfloat162 hi2, lo2;
        hi2.x = __float2bfloat16(v0);
        hi2.y = __float2bfloat16(v1);
        lo2.x = __float2bfloat16(v0 - __bfloat162float(hi2.x));
        lo2.y = __float2bfloat16(v1 - __bfloat162float(hi2.y));
        size_t o = ((size_t)nh * EE + e) * LL + s0 + 2 * s2;
        *(uint32_t*)(g_Vhi + o) = *(uint32_t*)&hi2;
        *(uint32_t*)(g_Vlo + o) = *(uint32_t*)&lo2;
    }
}

// ---------------------------------------------------------------------------
// attn: flash attention on HMMA (bf16 3-product split), cp.async pipelined.
// Block = 4 warps = 64 q-rows. K single-buffered (prefetch after QK phase),
// V double-buffered.
// ---------------------------------------------------------------------------
__global__ __launch_bounds__(128)
void attn_kernel(const float* __restrict__ mask, const float* __restrict__ keylen,
                 float* __restrict__ out) {
    extern __shared__ __nv_bfloat16 smem[];
    __nv_bfloat16* sKhi = smem;                              // [64][KSTR]
    __nv_bfloat16* sKlo = smem + 64 * KSTR;
    __nv_bfloat16* sVhi = smem + 2 * 64 * KSTR;              // [2][64][VSTR]
    __nv_bfloat16* sVlo = smem + 2 * 64 * KSTR + 2 * 64 * VSTR;

    const int tid  = threadIdx.x;
    const int w    = tid >> 5;
    const int lane = tid & 31;
    const int g    = lane >> 2, t = lane & 3;
    const int nh   = blockIdx.y;
    const int nb   = nh >> 3, h = nh & 7;
    const int l0   = blockIdx.x * BQ;
    const int row0 = l0 + w * 16 + g;

    const uint32_t bKhi = smem_u32(sKhi);
    const uint32_t bKlo = smem_u32(sKlo);
    const uint32_t bVhi = smem_u32(sVhi);
    const uint32_t bVlo = smem_u32(sVlo);

    const uint4* gKhiB = (const uint4*)(g_Khi + (size_t)nh * LL * DD);
    const uint4* gKloB = (const uint4*)(g_Klo + (size_t)nh * LL * DD);

    // issue cp.async group for tile it2 (K into single buf, V into buf vb)
    auto issue_tile = [&](int it2, int vb) {
        const uint4* gH = gKhiB + (size_t)it2 * 64 * DD / 8;
        const uint4* gL = gKloB + (size_t)it2 * 64 * DD / 8;
        #pragma unroll
        for (int i = 0; i < 12; i++) {
            int idx = tid + i * 128;
            int r = idx / 24, c = idx % 24;
            uint32_t off = (uint32_t)(r * KSTR + c * 8) * 2u;
            CP16(bKhi + off, gH + idx);
            CP16(bKlo + off, gL + idx);
        }
        #pragma unroll
        for (int i = 0; i < 4; i++) {
            int idx = tid + i * 128;
            int r = idx / 8, c = idx % 8;
            size_t go = ((size_t)nh * EE + r) * LL + it2 * 64 + c * 8;
            uint32_t off = (uint32_t)(vb * 64 * VSTR + r * VSTR + c * 8) * 2u;
            CP16(bVhi + off, (const uint4*)(g_Vhi + go));
            CP16(bVlo + off, (const uint4*)(g_Vlo + go));
        }
    };

    // prologue: prefetch tile 0
    issue_tile(0, 0);
    CP_COMMIT();

    // ---- Q fragments, register resident (reused for all 12 s-tiles) ----
    uint32_t aQh[12][4], aQl[12][4];
    {
        const __nv_bfloat16* qh = g_Qhi + ((size_t)nh * LL + row0) * DD;
        const __nv_bfloat16* ql = g_Qlo + ((size_t)nh * LL + row0) * DD;
        #pragma unroll
        for (int c = 0; c < 12; c++) {
            int d0 = c * 16 + 2 * t;
            aQh[c][0] = *(const uint32_t*)(qh + d0);
            aQh[c][1] = *(const uint32_t*)(qh + 8 * DD + d0);
            aQh[c][2] = *(const uint32_t*)(qh + d0 + 8);
            aQh[c][3] = *(const uint32_t*)(qh + 8 * DD + d0 + 8);
            aQl[c][0] = *(const uint32_t*)(ql + d0);
            aQl[c][1] = *(const uint32_t*)(ql + 8 * DD + d0);
            aQl[c][2] = *(const uint32_t*)(ql + d0 + 8);
            aQl[c][3] = *(const uint32_t*)(ql + 8 * DD + d0 + 8);
        }
    }

    float O[8][4];
    #pragma unroll
    for (int n = 0; n < 8; n++)
        #pragma unroll
        for (int j = 0; j < 4; j++) O[n][j] = 0.f;
    float m0 = -CUDART_INF_F, m1 = -CUDART_INF_F, ls0 = 0.f, ls1 = 0.f;

    const float* mrow0b = mask + (size_t)row0 * LL;
    const float* mrow1b = mrow0b + 8 * LL;
    const float* klb    = keylen + (size_t)nb * LL;

    for (int it = 0; it < NTILE; it++) {
        CP_WAIT0();
        __syncthreads();

        // ---- S = Q' K'^T : 8 n-tiles x 12 k-chunks x 3 products ----
        float S[8][4];
        #pragma unroll
        for (int n = 0; n < 8; n++)
            #pragma unroll
            for (int j = 0; j < 4; j++) S[n][j] = 0.f;

        #pragma unroll
        for (int n = 0; n < 8; n++) {
            const __nv_bfloat16* kh = sKhi + (n * 8 + g) * KSTR + 2 * t;
            const __nv_bfloat16* kl = sKlo + (n * 8 + g) * KSTR + 2 * t;
            #pragma unroll
            for (int c = 0; c < 12; c++) {
                uint32_t bh0 = *(const uint32_t*)(kh + c * 16);
                uint32_t bh1 = *(const uint32_t*)(kh + c * 16 + 8);
                uint32_t bl0 = *(const uint32_t*)(kl + c * 16);
                uint32_t bl1 = *(const uint32_t*)(kl + c * 16 + 8);
                mma_bf16(S[n], aQh[c], bh0, bh1);
                mma_bf16(S[n], aQh[c], bl0, bl1);
                mma_bf16(S[n], aQl[c], bh0, bh1);
            }
        }
        __syncthreads();   // all warps done reading K smem

        // prefetch next tile (K overwrites freed buffer; V into alternate buf)
        if (it + 1 < NTILE) issue_tile(it + 1, (it + 1) & 1);
        CP_COMMIT();

        // ---- bias: 0.125 * (mask + keylen) ----
        {
            const float* mr0 = mrow0b + it * 64;
            const float* mr1 = mrow1b + it * 64;
            const float* kl  = klb + it * 64;
            #pragma unroll
            for (int n = 0; n < 8; n++) {
                int sc = n * 8 + 2 * t;
                float2 a0 = *(const float2*)(mr0 + sc);
                float2 a1 = *(const float2*)(mr1 + sc);
                float2 kk = *(const float2*)(kl + sc);
                S[n][0] += 0.125f * (a0.x + kk.x);
                S[n][1] += 0.125f * (a0.y + kk.y);
                S[n][2] += 0.125f * (a1.x + kk.x);
                S[n][3] += 0.125f * (a1.y + kk.y);
            }
        }

        // ---- online softmax (rows quad-local) ----
        float mx0 = S[0][0], mx1 = S[0][2];
        #pragma unroll
        for (int n = 0; n < 8; n++) {
            mx0 = fmaxf(mx0, fmaxf(S[n][0], S[n][1]));
            mx1 = fmaxf(mx1, fmaxf(S[n][2], S[n][3]));
        }
        mx0 = fmaxf(mx0, __shfl_xor_sync(0xffffffffu, mx0, 1));
        mx0 = fmaxf(mx0, __shfl_xor_sync(0xffffffffu, mx0, 2));
        mx1 = fmaxf(mx1, __shfl_xor_sync(0xffffffffu, mx1, 1));
        mx1 = fmaxf(mx1, __shfl_xor_sync(0xffffffffu, mx1, 2));
        float m0n = fmaxf(m0, mx0), m1n = fmaxf(m1, mx1);
        float c0 = __expf(m0 - m0n), c1 = __expf(m1 - m1n);
        m0 = m0n; m1 = m1n;
        float s0 = 0.f, s1 = 0.f;
        #pragma unroll
        for (int n = 0; n < 8; n++) {
            S[n][0] = __expf(S[n][0] - m0n);
            S[n][1] = __expf(S[n][1] - m0n);
            S[n][2] = __expf(S[n][2] - m1n);
            S[n][3] = __expf(S[n][3] - m1n);
            s0 += S[n][0] + S[n][1];
            s1 += S[n][2] + S[n][3];
            O[n][0] *= c0; O[n][1] *= c0;
            O[n][2] *= c1; O[n][3] *= c1;
        }
        s0 += __shfl_xor_sync(0xffffffffu, s0, 1);
        s0 += __shfl_xor_sync(0xffffffffu, s0, 2);
        s1 += __shfl_xor_sync(0xffffffffu, s1, 1);
        s1 += __shfl_xor_sync(0xffffffffu, s1, 2);
        ls0 = ls0 * c0 + s0;
        ls1 = ls1 * c1 + s1;

        // ---- P -> bf16 hi/lo A-fragments (in-register) ----
        uint32_t ph[4][4], pl[4][4];
        #pragma unroll
        for (int kc = 0; kc < 4; kc++) {
            ph[kc][0] = pack_hi(S[2*kc][0],   S[2*kc][1],   pl[kc][0]);
            ph[kc][1] = pack_hi(S[2*kc][2],   S[2*kc][3],   pl[kc][1]);
            ph[kc][2] = pack_hi(S[2*kc+1][0], S[2*kc+1][1], pl[kc][2]);
            ph[kc][3] = pack_hi(S[2*kc+1][2], S[2*kc+1][3], pl[kc][3]);
        }

        // ---- O += P V : 8 e-tiles x 4 s-chunks x 3 products ----
        const __nv_bfloat16* vbH = sVhi + (it & 1) * 64 * VSTR;
        const __nv_bfloat16* vbL = sVlo + (it & 1) * 64 * VSTR;
        #pragma unroll
        for (int n = 0; n < 8; n++) {
            const __nv_bfloat16* vh = vbH + (n * 8 + g) * VSTR + 2 * t;
            const __nv_bfloat16* vl = vbL + (n * 8 + g) * VSTR + 2 * t;
            #pragma unroll
            for (int kc = 0; kc < 4; kc++) {
                uint32_t bh0 = *(const uint32_t*)(vh + kc * 16);
                uint32_t bh1 = *(const uint32_t*)(vh + kc * 16 + 8);
                uint32_t bl0 = *(const uint32_t*)(vl + kc * 16);
                uint32_t bl1 = *(const uint32_t*)(vl + kc * 16 + 8);
                mma_bf16(O[n], ph[kc], bh0, bh1);
                mma_bf16(O[n], ph[kc], bl0, bl1);
                mma_bf16(O[n], pl[kc], bh0, bh1);
            }
        }
    }

    // ---- epilogue ----
    float inv0 = 1.0f / ls0, inv1 = 1.0f / ls1;
    float* o0 = out + ((size_t)(nb * LL + row0) * HH + h) * EE;
    float* o1 = o0 + 8 * HH * EE;
    #pragma unroll
    for (int n = 0; n < 8; n++) {
        int e = n * 8 + 2 * t;
        *(float2*)(o0 + e) = make_float2(O[n][0] * inv0, O[n][1] * inv0);
        *(float2*)(o1 + e) = make_float2(O[n][2] * inv1, O[n][3] * inv1);
    }
}

// ---------------------------------------------------------------------------
extern "C" void kernel_launch(void* const* d_in, const int* in_sizes, int n_in,
                              void* d_out, int out_size) {
    const float* queries = (const float*)d_in[0];
    const float* keys    = (const float*)d_in[1];
    const float* values  = (const float*)d_in[2];
    const float* mask    = (const float*)d_in[3];
    const float* keylen  = (const float*)d_in[4];
    const float* freqs   = (const float*)d_in[5];
    const float* offsets = (const float*)d_in[6];
    const float* gains   = (const float*)d_in[7];
    const float* gate    = (const float*)d_in[8];
    float* out = (float*)d_out;

    prep_qk<<<dim3(LL / 16, NH), 256>>>(queries, keys, freqs, offsets, gains, gate);
    prep_v<<<dim3(NTILE, NH), 256>>>(values);

    const int smem = (2 * 64 * KSTR + 4 * 64 * VSTR) * 2;   // 88064 B
    cudaFuncSetAttribute(attn_kernel, cudaFuncAttributeMaxDynamicSharedMemorySize, smem);
    attn_kernel<<<dim3(LL / BQ, NH), 128, smem>>>(mask, keylen, out);
}

// round 6
// speedup vs baseline: 1.2674x; 1.0026x over previous
#include <cuda_runtime.h>
#include <cuda_bf16.h>
#include <math_constants.h>
#include <cstdint>

#define LL 768
#define HH 8
#define EE 64
#define NH 32
#define DD 192
#define BQ 64
#define NTILE 12
#define NITEMS 384          // 12 l-tiles x 32 nh
#define GRID_ATTN 304
#define KSTR 200            // padded smem row stride (bf16)
#define VSTR 72

// ---------------- scratch (device globals; no allocs) ----------------
__device__ __nv_bfloat16 g_Qhi[(size_t)NH * LL * DD];
__device__ __nv_bfloat16 g_Qlo[(size_t)NH * LL * DD];
__device__ __nv_bfloat16 g_Khi[(size_t)NH * LL * DD];
__device__ __nv_bfloat16 g_Klo[(size_t)NH * LL * DD];
__device__ __nv_bfloat16 g_Vhi[(size_t)NH * EE * LL];   // transposed [nh][e][s]
__device__ __nv_bfloat16 g_Vlo[(size_t)NH * EE * LL];
__device__ unsigned int  g_ctr;

// m16n8k16 row.col bf16 MMA, f32 accumulate
__device__ __forceinline__ void mma_bf16(float* c, const uint32_t* a, uint32_t b0, uint32_t b1) {
    asm volatile("mma.sync.aligned.m16n8k16.row.col.f32.bf16.bf16.f32 "
                 "{%0,%1,%2,%3}, {%4,%5,%6,%7}, {%8,%9}, {%0,%1,%2,%3};"
                 : "+f"(c[0]), "+f"(c[1]), "+f"(c[2]), "+f"(c[3])
                 : "r"(a[0]), "r"(a[1]), "r"(a[2]), "r"(a[3]), "r"(b0), "r"(b1));
}

__device__ __forceinline__ uint32_t smem_u32(const void* p) {
    uint32_t a;
    asm("{ .reg .u64 t; cvta.to.shared.u64 t, %1; cvt.u32.u64 %0, t; }" : "=r"(a) : "l"(p));
    return a;
}

#define CP16(dst, src) asm volatile("cp.async.cg.shared.global [%0], [%1], 16;" :: "r"(dst), "l"(src))
#define CP_COMMIT()    asm volatile("cp.async.commit_group;" ::: "memory")
#define CP_WAIT0()     asm volatile("cp.async.wait_group 0;" ::: "memory")

__device__ __forceinline__ uint32_t pack_hi(float x, float y, uint32_t& lo) {
    __nv_bfloat162 h2;
    h2.x = __float2bfloat16(x);
    h2.y = __float2bfloat16(y);
    __nv_bfloat162 l2;
    l2.x = __float2bfloat16(x - __bfloat162float(h2.x));
    l2.y = __float2bfloat16(y - __bfloat162float(h2.y));
    lo = *(uint32_t*)&l2;
    return *(uint32_t*)&h2;
}

// ---------------------------------------------------------------------------
// prep_qk: augmented Q'/K' (d=192) bf16 hi/lo. One exact sincos at l0,
// then phase rotation (4 FMA) for the next 3 positions. Also seeds g_ctr.
// ---------------------------------------------------------------------------
__global__ void prep_qk(const float* __restrict__ q, const float* __restrict__ k,
                        const float* __restrict__ freqs, const float* __restrict__ offsets,
                        const float* __restrict__ gains, const float* __restrict__ gate) {
    if (blockIdx.x == 0 && blockIdx.y == 0 && threadIdx.x == 0)
        g_ctr = GRID_ATTN;                    // seed work queue for attn (runs first in stream)

    int e  = threadIdx.x & 63;
    int j  = threadIdx.x >> 6;                // 0..3
    int l0 = blockIdx.x * 16 + j * 4;         // grid.x = 48
    int nh = blockIdx.y;
    int n = nh >> 3, h = nh & 7;
    int he = h * 64 + e;

    float fr  = freqs[he];
    float f   = 0.5f / (1.0f + __expf(-fr));
    float off = offsets[he];
    float gn  = gains[he];
    float g   = (gn > 8.0f) ? gn : __logf(1.0f + __expf(gn));
    float gt  = gate[he];
    float c   = (1.0f - gt) * g * g;

    // exact-ish phase at l0
    float lf    = (float)l0;
    float fl    = f * lf;
    float resid = fmaf(f, lf, -fl);
    float frac  = (fl - floorf(fl)) + resid;
    const float TWO_PI = 6.28318530717958647692f;
    float phk   = TWO_PI * frac;
    float argq  = phk + off;
    float cq = __cosf(argq), sq = __sinf(argq);
    float ck = __cosf(phk),  sk = __sinf(phk);
    // per-step rotation
    float dph = TWO_PI * f;
    float cF = __cosf(dph), sF = __sinf(dph);

    #pragma unroll
    for (int dl = 0; dl < 4; dl++) {
        int l = l0 + dl;
        size_t qi = ((size_t)(n * LL + l) * HH + h) * EE + e;
        float qv = q[qi] * 0.125f;            // softmax temp folded into Q'
        float kv = k[qi];

        float qs[3] = { qv * gt, qv * c * cq, qv * c * sq };
        float ks[3] = { kv,      kv * ck,     kv * sk     };

        size_t base = ((size_t)nh * LL + l) * DD;
        #pragma unroll
        for (int kk = 0; kk < 3; kk++) {
            float v = qs[kk];
            __nv_bfloat16 hi = __float2bfloat16(v);
            g_Qhi[base + kk * 64 + e] = hi;
            g_Qlo[base + kk * 64 + e] = __float2bfloat16(v - __bfloat162float(hi));
            float w = ks[kk];
            __nv_bfloat16 whi = __float2bfloat16(w);
            g_Khi[base + kk * 64 + e] = whi;
            g_Klo[base + kk * 64 + e] = __float2bfloat16(w - __bfloat162float(whi));
        }
        // rotate phases by 2*pi*f
        float cq2 = cq * cF - sq * sF, sq2 = sq * cF + cq * sF;
        float ck2 = ck * cF - sk * sF, sk2 = sk * cF + ck * sF;
        cq = cq2; sq = sq2; ck = ck2; sk = sk2;
    }
}

// ---------------------------------------------------------------------------
// prep_v: V transposed to [nh][e][s] bf16 hi/lo (s contiguous).
// ---------------------------------------------------------------------------
__global__ void prep_v(const float* __restrict__ values) {
    __shared__ float sm[64 * 65];
    int t = blockIdx.x, nh = blockIdx.y;
    int n = nh >> 3, h = nh & 7;
    int s0 = t * 64;

    #pragma unroll
    for (int i = 0; i < 16; i++) {
        int idx = threadIdx.x + i * 256;
        int r = idx >> 6, e = idx & 63;
        sm[e * 65 + r] = values[((size_t)(n * LL + s0 + r) * HH + h) * EE + e];
    }
    __syncthreads();

    #pragma unroll
    for (int i = 0; i < 8; i++) {
        int pid = threadIdx.x + i * 256;
        int e = pid >> 5, s2 = pid & 31;
        float v0 = sm[e * 65 + 2 * s2];
        float v1 = sm[e * 65 + 2 * s2 + 1];
        __nv_bfloat162 hi2, lo2;
        hi2.x = __float2bfloat16(v0);
        hi2.y = __float2bfloat16(v1);
        lo2.x = __float2bfloat16(v0 - __bfloat162float(hi2.x));
        lo2.y = __float2bfloat16(v1 - __bfloat162float(hi2.y));
        size_t o = ((size_t)nh * EE + e) * LL + s0 + 2 * s2;
        *(uint32_t*)(g_Vhi + o) = *(uint32_t*)&hi2;
        *(uint32_t*)(g_Vlo + o) = *(uint32_t*)&lo2;
    }
}

// ---------------------------------------------------------------------------
// attn: persistent work-queue flash attention on HMMA (bf16 3-product),
// cp.async pipelined. Item = (nh, l-tile). grid = GRID_ATTN CTAs.
// ---------------------------------------------------------------------------
__global__ __launch_bounds__(128)
void attn_kernel(const float* __restrict__ mask, const float* __restrict__ keylen,
                 float* __restrict__ out) {
    extern __shared__ __nv_bfloat16 smem[];
    __nv_bfloat16* sKhi = smem;                              // [64][KSTR]
    __nv_bfloat16* sKlo = smem + 64 * KSTR;
    __nv_bfloat16* sVhi = smem + 2 * 64 * KSTR;              // [2][64][VSTR]
    __nv_bfloat16* sVlo = smem + 2 * 64 * KSTR + 2 * 64 * VSTR;

    const int tid  = threadIdx.x;
    const int w    = tid >> 5;
    const int lane = tid & 31;
    const int g    = lane >> 2, t = lane & 3;

    const uint32_t bKhi = smem_u32(sKhi);
    const uint32_t bKlo = smem_u32(sKlo);
    const uint32_t bVhi = smem_u32(sVhi);
    const uint32_t bVlo = smem_u32(sVlo);

    // precomputed per-thread cp.async source/dest indices
    unsigned item = blockIdx.x;
    while (item < NITEMS) {
        const int nh = (int)(item / NTILE);
        const int lt = (int)(item % NTILE);
        const int nb = nh >> 3, h = nh & 7;
        const int l0 = lt * BQ;
        const int row0 = l0 + w * 16 + g;

        const uint4* gKhiB = (const uint4*)(g_Khi + (size_t)nh * LL * DD);
        const uint4* gKloB = (const uint4*)(g_Klo + (size_t)nh * LL * DD);

        // issue cp.async group for tile it2 (K single buf, V buf vb)
        auto issue_tile = [&](int it2, int vb) {
            const uint4* gH = gKhiB + (size_t)it2 * 64 * DD / 8;
            const uint4* gL = gKloB + (size_t)it2 * 64 * DD / 8;
            #pragma unroll
            for (int i = 0; i < 12; i++) {
                int idx = tid + i * 128;
                int r = idx / 24, c = idx % 24;
                uint32_t off = (uint32_t)(r * KSTR + c * 8) * 2u;
                CP16(bKhi + off, gH + idx);
                CP16(bKlo + off, gL + idx);
            }
            #pragma unroll
            for (int i = 0; i < 4; i++) {
                int idx = tid + i * 128;
                int r = idx / 8, c = idx % 8;
                size_t go = ((size_t)nh * EE + r) * LL + it2 * 64 + c * 8;
                uint32_t off = (uint32_t)(vb * 64 * VSTR + r * VSTR + c * 8) * 2u;
                CP16(bVhi + off, (const uint4*)(g_Vhi + go));
                CP16(bVlo + off, (const uint4*)(g_Vlo + go));
            }
        };

        issue_tile(0, 0);
        CP_COMMIT();

        // ---- Q fragments (register resident for this item) ----
        uint32_t aQh[12][4], aQl[12][4];
        {
            const __nv_bfloat16* qh = g_Qhi + ((size_t)nh * LL + row0) * DD;
            const __nv_bfloat16* ql = g_Qlo + ((size_t)nh * LL + row0) * DD;
            #pragma unroll
            for (int c = 0; c < 12; c++) {
                int d0 = c * 16 + 2 * t;
                aQh[c][0] = *(const uint32_t*)(qh + d0);
                aQh[c][1] = *(const uint32_t*)(qh + 8 * DD + d0);
                aQh[c][2] = *(const uint32_t*)(qh + d0 + 8);
                aQh[c][3] = *(const uint32_t*)(qh + 8 * DD + d0 + 8);
                aQl[c][0] = *(const uint32_t*)(ql + d0);
                aQl[c][1] = *(const uint32_t*)(ql + 8 * DD + d0);
                aQl[c][2] = *(const uint32_t*)(ql + d0 + 8);
                aQl[c][3] = *(const uint32_t*)(ql + 8 * DD + d0 + 8);
            }
        }

        float O[8][4];
        #pragma unroll
        for (int n = 0; n < 8; n++)
            #pragma unroll
            for (int j = 0; j < 4; j++) O[n][j] = 0.f;
        float m0 = -CUDART_INF_F, m1 = -CUDART_INF_F, ls0 = 0.f, ls1 = 0.f;

        const float* mrow0b = mask + (size_t)row0 * LL;
        const float* mrow1b = mrow0b + 8 * LL;
        const float* klb    = keylen + (size_t)nb * LL;

        for (int it = 0; it < NTILE; it++) {
            CP_WAIT0();
            __syncthreads();

            // ---- S = Q' K'^T ----
            float S[8][4];
            #pragma unroll
            for (int n = 0; n < 8; n++)
                #pragma unroll
                for (int j = 0; j < 4; j++) S[n][j] = 0.f;

            #pragma unroll
            for (int n = 0; n < 8; n++) {
                const __nv_bfloat16* kh = sKhi + (n * 8 + g) * KSTR + 2 * t;
                const __nv_bfloat16* kl = sKlo + (n * 8 + g) * KSTR + 2 * t;
                #pragma unroll
                for (int c = 0; c < 12; c++) {
                    uint32_t bh0 = *(const uint32_t*)(kh + c * 16);
                    uint32_t bh1 = *(const uint32_t*)(kh + c * 16 + 8);
                    uint32_t bl0 = *(const uint32_t*)(kl + c * 16);
                    uint32_t bl1 = *(const uint32_t*)(kl + c * 16 + 8);
                    mma_bf16(S[n], aQh[c], bh0, bh1);
                    mma_bf16(S[n], aQh[c], bl0, bl1);
                    mma_bf16(S[n], aQl[c], bh0, bh1);
                }
            }
            __syncthreads();   // all warps done reading K smem

            if (it + 1 < NTILE) { issue_tile(it + 1, (it + 1) & 1); }
            CP_COMMIT();

            // ---- bias ----
            {
                const float* mr0 = mrow0b + it * 64;
                const float* mr1 = mrow1b + it * 64;
                const float* kl  = klb + it * 64;
                #pragma unroll
                for (int n = 0; n < 8; n++) {
                    int sc = n * 8 + 2 * t;
                    float2 a0 = *(const float2*)(mr0 + sc);
                    float2 a1 = *(const float2*)(mr1 + sc);
                    float2 kk = *(const float2*)(kl + sc);
                    S[n][0] += 0.125f * (a0.x + kk.x);
                    S[n][1] += 0.125f * (a0.y + kk.y);
                    S[n][2] += 0.125f * (a1.x + kk.x);
                    S[n][3] += 0.125f * (a1.y + kk.y);
                }
            }

            // ---- online softmax (rows quad-local) ----
            float mx0 = S[0][0], mx1 = S[0][2];
            #pragma unroll
            for (int n = 0; n < 8; n++) {
                mx0 = fmaxf(mx0, fmaxf(S[n][0], S[n][1]));
                mx1 = fmaxf(mx1, fmaxf(S[n][2], S[n][3]));
            }
            mx0 = fmaxf(mx0, __shfl_xor_sync(0xffffffffu, mx0, 1));
            mx0 = fmaxf(mx0, __shfl_xor_sync(0xffffffffu, mx0, 2));
            mx1 = fmaxf(mx1, __shfl_xor_sync(0xffffffffu, mx1, 1));
            mx1 = fmaxf(mx1, __shfl_xor_sync(0xffffffffu, mx1, 2));
            float m0n = fmaxf(m0, mx0), m1n = fmaxf(m1, mx1);
            float c0 = __expf(m0 - m0n), c1 = __expf(m1 - m1n);
            m0 = m0n; m1 = m1n;
            float s0 = 0.f, s1 = 0.f;
            #pragma unroll
            for (int n = 0; n < 8; n++) {
                S[n][0] = __expf(S[n][0] - m0n);
                S[n][1] = __expf(S[n][1] - m0n);
                S[n][2] = __expf(S[n][2] - m1n);
                S[n][3] = __expf(S[n][3] - m1n);
                s0 += S[n][0] + S[n][1];
                s1 += S[n][2] + S[n][3];
                O[n][0] *= c0; O[n][1] *= c0;
                O[n][2] *= c1; O[n][3] *= c1;
            }
            s0 += __shfl_xor_sync(0xffffffffu, s0, 1);
            s0 += __shfl_xor_sync(0xffffffffu, s0, 2);
            s1 += __shfl_xor_sync(0xffffffffu, s1, 1);
            s1 += __shfl_xor_sync(0xffffffffu, s1, 2);
            ls0 = ls0 * c0 + s0;
            ls1 = ls1 * c1 + s1;

            // ---- P -> bf16 hi/lo A-fragments (in-register) ----
            uint32_t ph[4][4], pl[4][4];
            #pragma unroll
            for (int kc = 0; kc < 4; kc++) {
                ph[kc][0] = pack_hi(S[2*kc][0],   S[2*kc][1],   pl[kc][0]);
                ph[kc][1] = pack_hi(S[2*kc][2],   S[2*kc][3],   pl[kc][1]);
                ph[kc][2] = pack_hi(S[2*kc+1][0], S[2*kc+1][1], pl[kc][2]);
                ph[kc][3] = pack_hi(S[2*kc+1][2], S[2*kc+1][3], pl[kc][3]);
            }

            // ---- O += P V ----
            const __nv_bfloat16* vbH = sVhi + (it & 1) * 64 * VSTR;
            const __nv_bfloat16* vbL = sVlo + (it & 1) * 64 * VSTR;
            #pragma unroll
            for (int n = 0; n < 8; n++) {
                const __nv_bfloat16* vh = vbH + (n * 8 + g) * VSTR + 2 * t;
                const __nv_bfloat16* vl = vbL + (n * 8 + g) * VSTR + 2 * t;
                #pragma unroll
                for (int kc = 0; kc < 4; kc++) {
                    uint32_t bh0 = *(const uint32_t*)(vh + kc * 16);
                    uint32_t bh1 = *(const uint32_t*)(vh + kc * 16 + 8);
                    uint32_t bl0 = *(const uint32_t*)(vl + kc * 16);
                    uint32_t bl1 = *(const uint32_t*)(vl + kc * 16 + 8);
                    mma_bf16(O[n], ph[kc], bh0, bh1);
                    mma_bf16(O[n], ph[kc], bl0, bl1);
                    mma_bf16(O[n], pl[kc], bh0, bh1);
                }
            }
        }

        // ---- epilogue for this item ----
        float inv0 = 1.0f / ls0, inv1 = 1.0f / ls1;
        float* o0 = out + ((size_t)(nb * LL + row0) * HH + h) * EE;
        float* o1 = o0 + 8 * HH * EE;
        #pragma unroll
        for (int n = 0; n < 8; n++) {
            int e = n * 8 + 2 * t;
            *(float2*)(o0 + e) = make_float2(O[n][0] * inv0, O[n][1] * inv0);
            *(float2*)(o1 + e) = make_float2(O[n][2] * inv1, O[n][3] * inv1);
        }

        // ---- next work item ----
        __shared__ unsigned s_item;
        __syncthreads();
        if (tid == 0) s_item = atomicAdd(&g_ctr, 1u);
        __syncthreads();
        item = s_item;
    }
}

// ---------------------------------------------------------------------------
extern "C" void kernel_launch(void* const* d_in, const int* in_sizes, int n_in,
                              void* d_out, int out_size) {
    const float* queries = (const float*)d_in[0];
    const float* keys    = (const float*)d_in[1];
    const float* values  = (const float*)d_in[2];
    const float* mask    = (const float*)d_in[3];
    const float* keylen  = (const float*)d_in[4];
    const float* freqs   = (const float*)d_in[5];
    const float* offsets = (const float*)d_in[6];
    const float* gains   = (const float*)d_in[7];
    const float* gate    = (const float*)d_in[8];
    float* out = (float*)d_out;

    prep_qk<<<dim3(LL / 16, NH), 256>>>(queries, keys, freqs, offsets, gains, gate);
    prep_v<<<dim3(NTILE, NH), 256>>>(values);

    const int smem = (2 * 64 * KSTR + 4 * 64 * VSTR) * 2;   // 88064 B
    cudaFuncSetAttribute(attn_kernel, cudaFuncAttributeMaxDynamicSharedMemorySize, smem);
    attn_kernel<<<GRID_ATTN, 128, smem>>>(mask, keylen, out);
}

// round 7
// speedup vs baseline: 1.2936x; 1.0207x over previous
#include <cuda_runtime.h>
#include <cuda_bf16.h>
#include <math_constants.h>
#include <cstdint>

#define LL 768
#define HH 8
#define EE 64
#define NH 32
#define DD 192
#define BQ 64
#define NTILE 12
#define NITEMS 384          // 12 l-tiles x 32 nh
#define GRID_ATTN 304
#define KSTR 200            // padded smem row stride (bf16)
#define VSTR 72

// ---------------- scratch (device globals; no allocs) ----------------
// d-layout: d = e for gate channel (0..63); d = 64+2e (cos), 65+2e (sin).
__device__ __nv_bfloat16 g_Qhi[(size_t)NH * LL * DD];
__device__ __nv_bfloat16 g_Qlo[(size_t)NH * LL * DD];
__device__ __nv_bfloat16 g_Khi[(size_t)NH * LL * DD];
__device__ __nv_bfloat16 g_Klo[(size_t)NH * LL * DD];
__device__ __nv_bfloat16 g_Vhi[(size_t)NH * EE * LL];   // transposed [nh][e][s]
__device__ __nv_bfloat16 g_Vlo[(size_t)NH * EE * LL];
__device__ unsigned int  g_ctr;

// m16n8k16 row.col bf16 MMA, f32 accumulate
__device__ __forceinline__ void mma_bf16(float* c, const uint32_t* a, uint32_t b0, uint32_t b1) {
    asm volatile("mma.sync.aligned.m16n8k16.row.col.f32.bf16.bf16.f32 "
                 "{%0,%1,%2,%3}, {%4,%5,%6,%7}, {%8,%9}, {%0,%1,%2,%3};"
                 : "+f"(c[0]), "+f"(c[1]), "+f"(c[2]), "+f"(c[3])
                 : "r"(a[0]), "r"(a[1]), "r"(a[2]), "r"(a[3]), "r"(b0), "r"(b1));
}

__device__ __forceinline__ uint32_t smem_u32(const void* p) {
    uint32_t a;
    asm("{ .reg .u64 t; cvta.to.shared.u64 t, %1; cvt.u32.u64 %0, t; }" : "=r"(a) : "l"(p));
    return a;
}

#define CP16(dst, src) asm volatile("cp.async.cg.shared.global [%0], [%1], 16;" :: "r"(dst), "l"(src))
#define CP_COMMIT()    asm volatile("cp.async.commit_group;" ::: "memory")
#define CP_WAIT0()     asm volatile("cp.async.wait_group 0;" ::: "memory")

__device__ __forceinline__ uint32_t pack_hi(float x, float y, uint32_t& lo) {
    __nv_bfloat162 h2;
    h2.x = __float2bfloat16(x);
    h2.y = __float2bfloat16(y);
    __nv_bfloat162 l2;
    l2.x = __float2bfloat16(x - __bfloat162float(h2.x));
    l2.y = __float2bfloat16(y - __bfloat162float(h2.y));
    lo = *(uint32_t*)&l2;
    return *(uint32_t*)&h2;
}

__device__ __forceinline__ uint32_t bf2_pack(float x, float y) {
    __nv_bfloat162 h2;
    h2.x = __float2bfloat16(x);
    h2.y = __float2bfloat16(y);
    return *(uint32_t*)&h2;
}

// ---------------------------------------------------------------------------
// prep (fused): blockIdx.x < 48 -> Q'/K' build; else -> V transpose.
// ---------------------------------------------------------------------------
__global__ void prep_kernel(const float* __restrict__ q, const float* __restrict__ k,
                            const float* __restrict__ values,
                            const float* __restrict__ freqs, const float* __restrict__ offsets,
                            const float* __restrict__ gains, const float* __restrict__ gate) {
    const int nh = blockIdx.y;
    const int n = nh >> 3, h = nh & 7;

    if (blockIdx.x < 48) {
        // ---------------- Q'/K' part ----------------
        if (blockIdx.x == 0 && blockIdx.y == 0 && threadIdx.x == 0)
            g_ctr = GRID_ATTN;                // seed attn work queue

        int e  = threadIdx.x & 63;
        int j  = threadIdx.x >> 6;            // 0..3
        int l0 = blockIdx.x * 16 + j * 4;
        int he = h * 64 + e;

        float fr  = freqs[he];
        float f   = 0.5f / (1.0f + __expf(-fr));
        float off = offsets[he];
        float gn  = gains[he];
        float g   = (gn > 8.0f) ? gn : __logf(1.0f + __expf(gn));
        float gt  = gate[he];
        float c   = (1.0f - gt) * g * g;

        float lf    = (float)l0;
        float fl    = f * lf;
        float resid = fmaf(f, lf, -fl);
        float frac  = (fl - floorf(fl)) + resid;
        const float TWO_PI = 6.28318530717958647692f;
        float phk   = TWO_PI * frac;
        float argq  = phk + off;
        float cq = __cosf(argq), sq = __sinf(argq);
        float ck = __cosf(phk),  sk = __sinf(phk);
        float dph = TWO_PI * f;
        float cF = __cosf(dph), sF = __sinf(dph);

        #pragma unroll
        for (int dl = 0; dl < 4; dl++) {
            int l = l0 + dl;
            size_t qi = ((size_t)(n * LL + l) * HH + h) * EE + e;
            float qv = q[qi] * 0.125f;        // softmax temp folded into Q'
            float kv = k[qi];

            size_t base = ((size_t)nh * LL + l) * DD;

            // gate channel (d = e), 2-byte stores
            {
                float v = qv * gt;
                __nv_bfloat16 hi = __float2bfloat16(v);
                g_Qhi[base + e] = hi;
                g_Qlo[base + e] = __float2bfloat16(v - __bfloat162float(hi));
                __nv_bfloat16 whi = __float2bfloat16(kv);
                g_Khi[base + e] = whi;
                g_Klo[base + e] = __float2bfloat16(kv - __bfloat162float(whi));
            }
            // cos/sin channels (d = 64+2e, 65+2e), one 4-byte store each
            {
                float qc = qv * c;
                float vx = qc * cq, vy = qc * sq;
                uint32_t lo;
                uint32_t hi = pack_hi(vx, vy, lo);
                *(uint32_t*)(g_Qhi + base + 64 + 2 * e) = hi;
                *(uint32_t*)(g_Qlo + base + 64 + 2 * e) = lo;
                float wx = kv * ck, wy = kv * sk;
                uint32_t wlo;
                uint32_t whi = pack_hi(wx, wy, wlo);
                *(uint32_t*)(g_Khi + base + 64 + 2 * e) = whi;
                *(uint32_t*)(g_Klo + base + 64 + 2 * e) = wlo;
            }
            // rotate phases by 2*pi*f
            float cq2 = cq * cF - sq * sF, sq2 = sq * cF + cq * sF;
            float ck2 = ck * cF - sk * sF, sk2 = sk * cF + ck * sF;
            cq = cq2; sq = sq2; ck = ck2; sk = sk2;
        }
    } else {
        // ---------------- V transpose part ----------------
        __shared__ float sm[64 * 65];
        int t = blockIdx.x - 48;
        int s0 = t * 64;

        #pragma unroll
        for (int i = 0; i < 16; i++) {
            int idx = threadIdx.x + i * 256;
            int r = idx >> 6, e = idx & 63;
            sm[e * 65 + r] = values[((size_t)(n * LL + s0 + r) * HH + h) * EE + e];
        }
        __syncthreads();

        #pragma unroll
        for (int i = 0; i < 8; i++) {
            int pid = threadIdx.x + i * 256;
            int e = pid >> 5, s2 = pid & 31;
            float v0 = sm[e * 65 + 2 * s2];
            float v1 = sm[e * 65 + 2 * s2 + 1];
            uint32_t lo;
            uint32_t hi = pack_hi(v0, v1, lo);
            size_t o = ((size_t)nh * EE + e) * LL + s0 + 2 * s2;
            *(uint32_t*)(g_Vhi + o) = hi;
            *(uint32_t*)(g_Vlo + o) = lo;
        }
    }
}

// ---------------------------------------------------------------------------
// attn: persistent work-queue flash attention on HMMA (bf16 3-product),
// cp.async pipelined. Item = (nh, l-tile). grid = GRID_ATTN CTAs.
// ---------------------------------------------------------------------------
__global__ __launch_bounds__(128)
void attn_kernel(const float* __restrict__ mask, const float* __restrict__ keylen,
                 float* __restrict__ out) {
    extern __shared__ __nv_bfloat16 smem[];
    __nv_bfloat16* sKhi = smem;                              // [64][KSTR]
    __nv_bfloat16* sKlo = smem + 64 * KSTR;
    __nv_bfloat16* sVhi = smem + 2 * 64 * KSTR;              // [2][64][VSTR]
    __nv_bfloat16* sVlo = smem + 2 * 64 * KSTR + 2 * 64 * VSTR;

    const int tid  = threadIdx.x;
    const int w    = tid >> 5;
    const int lane = tid & 31;
    const int g    = lane >> 2, t = lane & 3;

    const uint32_t bKhi = smem_u32(sKhi);
    const uint32_t bKlo = smem_u32(sKlo);
    const uint32_t bVhi = smem_u32(sVhi);
    const uint32_t bVlo = smem_u32(sVlo);

    unsigned item = blockIdx.x;
    while (item < NITEMS) {
        const int nh = (int)(item / NTILE);
        const int lt = (int)(item % NTILE);
        const int nb = nh >> 3, h = nh & 7;
        const int l0 = lt * BQ;
        const int row0 = l0 + w * 16 + g;

        const uint4* gKhiB = (const uint4*)(g_Khi + (size_t)nh * LL * DD);
        const uint4* gKloB = (const uint4*)(g_Klo + (size_t)nh * LL * DD);

        auto issue_tile = [&](int it2, int vb) {
            const uint4* gH = gKhiB + (size_t)it2 * 64 * DD / 8;
            const uint4* gL = gKloB + (size_t)it2 * 64 * DD / 8;
            #pragma unroll
            for (int i = 0; i < 12; i++) {
                int idx = tid + i * 128;
                int r = idx / 24, c = idx % 24;
                uint32_t off = (uint32_t)(r * KSTR + c * 8) * 2u;
                CP16(bKhi + off, gH + idx);
                CP16(bKlo + off, gL + idx);
            }
            #pragma unroll
            for (int i = 0; i < 4; i++) {
                int idx = tid + i * 128;
                int r = idx / 8, c = idx % 8;
                size_t go = ((size_t)nh * EE + r) * LL + it2 * 64 + c * 8;
                uint32_t off = (uint32_t)(vb * 64 * VSTR + r * VSTR + c * 8) * 2u;
                CP16(bVhi + off, (const uint4*)(g_Vhi + go));
                CP16(bVlo + off, (const uint4*)(g_Vlo + go));
            }
        };

        issue_tile(0, 0);
        CP_COMMIT();

        // ---- Q fragments (register resident for this item) ----
        uint32_t aQh[12][4], aQl[12][4];
        {
            const __nv_bfloat16* qh = g_Qhi + ((size_t)nh * LL + row0) * DD;
            const __nv_bfloat16* ql = g_Qlo + ((size_t)nh * LL + row0) * DD;
            #pragma unroll
            for (int c = 0; c < 12; c++) {
                int d0 = c * 16 + 2 * t;
                aQh[c][0] = *(const uint32_t*)(qh + d0);
                aQh[c][1] = *(const uint32_t*)(qh + 8 * DD + d0);
                aQh[c][2] = *(const uint32_t*)(qh + d0 + 8);
                aQh[c][3] = *(const uint32_t*)(qh + 8 * DD + d0 + 8);
                aQl[c][0] = *(const uint32_t*)(ql + d0);
                aQl[c][1] = *(const uint32_t*)(ql + 8 * DD + d0);
                aQl[c][2] = *(const uint32_t*)(ql + d0 + 8);
                aQl[c][3] = *(const uint32_t*)(ql + 8 * DD + d0 + 8);
            }
        }

        float O[8][4];
        #pragma unroll
        for (int n = 0; n < 8; n++)
            #pragma unroll
            for (int j = 0; j < 4; j++) O[n][j] = 0.f;
        float m0 = -CUDART_INF_F, m1 = -CUDART_INF_F, ls0 = 0.f, ls1 = 0.f;

        const float* mrow0b = mask + (size_t)row0 * LL;
        const float* mrow1b = mrow0b + 8 * LL;
        const float* klb    = keylen + (size_t)nb * LL;

        for (int it = 0; it < NTILE; it++) {
            CP_WAIT0();
            __syncthreads();

            // ---- S = Q' K'^T ----
            float S[8][4];
            #pragma unroll
            for (int n = 0; n < 8; n++)
                #pragma unroll
                for (int j = 0; j < 4; j++) S[n][j] = 0.f;

            #pragma unroll
            for (int n = 0; n < 8; n++) {
                const __nv_bfloat16* kh = sKhi + (n * 8 + g) * KSTR + 2 * t;
                const __nv_bfloat16* kl = sKlo + (n * 8 + g) * KSTR + 2 * t;
                #pragma unroll
                for (int c = 0; c < 12; c++) {
                    uint32_t bh0 = *(const uint32_t*)(kh + c * 16);
                    uint32_t bh1 = *(const uint32_t*)(kh + c * 16 + 8);
                    uint32_t bl0 = *(const uint32_t*)(kl + c * 16);
                    uint32_t bl1 = *(const uint32_t*)(kl + c * 16 + 8);
                    mma_bf16(S[n], aQh[c], bh0, bh1);
                    mma_bf16(S[n], aQh[c], bl0, bl1);
                    mma_bf16(S[n], aQl[c], bh0, bh1);
                }
            }
            __syncthreads();   // all warps done reading K smem

            if (it + 1 < NTILE) { issue_tile(it + 1, (it + 1) & 1); }
            CP_COMMIT();

            // ---- bias: 0.125 * (mask + keylen) ----
            {
                const float* mr0 = mrow0b + it * 64;
                const float* mr1 = mrow1b + it * 64;
                const float* kl  = klb + it * 64;
                #pragma unroll
                for (int n = 0; n < 8; n++) {
                    int sc = n * 8 + 2 * t;
                    float2 a0 = *(const float2*)(mr0 + sc);
                    float2 a1 = *(const float2*)(mr1 + sc);
                    float2 kk = *(const float2*)(kl + sc);
                    S[n][0] += 0.125f * (a0.x + kk.x);
                    S[n][1] += 0.125f * (a0.y + kk.y);
                    S[n][2] += 0.125f * (a1.x + kk.x);
                    S[n][3] += 0.125f * (a1.y + kk.y);
                }
            }

            // ---- online softmax (rows quad-local) ----
            float mx0 = S[0][0], mx1 = S[0][2];
            #pragma unroll
            for (int n = 0; n < 8; n++) {
                mx0 = fmaxf(mx0, fmaxf(S[n][0], S[n][1]));
                mx1 = fmaxf(mx1, fmaxf(S[n][2], S[n][3]));
            }
            mx0 = fmaxf(mx0, __shfl_xor_sync(0xffffffffu, mx0, 1));
            mx0 = fmaxf(mx0, __shfl_xor_sync(0xffffffffu, mx0, 2));
            mx1 = fmaxf(mx1, __shfl_xor_sync(0xffffffffu, mx1, 1));
            mx1 = fmaxf(mx1, __shfl_xor_sync(0xffffffffu, mx1, 2));
            float m0n = fmaxf(m0, mx0), m1n = fmaxf(m1, mx1);
            float c0 = __expf(m0 - m0n), c1 = __expf(m1 - m1n);
            m0 = m0n; m1 = m1n;
            float s0 = 0.f, s1 = 0.f;
            #pragma unroll
            for (int n = 0; n < 8; n++) {
                S[n][0] = __expf(S[n][0] - m0n);
                S[n][1] = __expf(S[n][1] - m0n);
                S[n][2] = __expf(S[n][2] - m1n);
                S[n][3] = __expf(S[n][3] - m1n);
                s0 += S[n][0] + S[n][1];
                s1 += S[n][2] + S[n][3];
                O[n][0] *= c0; O[n][1] *= c0;
                O[n][2] *= c1; O[n][3] *= c1;
            }
            s0 += __shfl_xor_sync(0xffffffffu, s0, 1);
            s0 += __shfl_xor_sync(0xffffffffu, s0, 2);
            s1 += __shfl_xor_sync(0xffffffffu, s1, 1);
            s1 += __shfl_xor_sync(0xffffffffu, s1, 2);
            ls0 = ls0 * c0 + s0;
            ls1 = ls1 * c1 + s1;

            // ---- P -> bf16 hi/lo A-fragments (in-register) ----
            uint32_t ph[4][4], pl[4][4];
            #pragma unroll
            for (int kc = 0; kc < 4; kc++) {
                ph[kc][0] = pack_hi(S[2*kc][0],   S[2*kc][1],   pl[kc][0]);
                ph[kc][1] = pack_hi(S[2*kc][2],   S[2*kc][3],   pl[kc][1]);
                ph[kc][2] = pack_hi(S[2*kc+1][0], S[2*kc+1][1], pl[kc][2]);
                ph[kc][3] = pack_hi(S[2*kc+1][2], S[2*kc+1][3], pl[kc][3]);
            }

            // ---- O += P V ----
            const __nv_bfloat16* vbH = sVhi + (it & 1) * 64 * VSTR;
            const __nv_bfloat16* vbL = sVlo + (it & 1) * 64 * VSTR;
            #pragma unroll
            for (int n = 0; n < 8; n++) {
                const __nv_bfloat16* vh = vbH + (n * 8 + g) * VSTR + 2 * t;
                const __nv_bfloat16* vl = vbL + (n * 8 + g) * VSTR + 2 * t;
                #pragma unroll
                for (int kc = 0; kc < 4; kc++) {
                    uint32_t bh0 = *(const uint32_t*)(vh + kc * 16);
                    uint32_t bh1 = *(const uint32_t*)(vh + kc * 16 + 8);
                    uint32_t bl0 = *(const uint32_t*)(vl + kc * 16);
                    uint32_t bl1 = *(const uint32_t*)(vl + kc * 16 + 8);
                    mma_bf16(O[n], ph[kc], bh0, bh1);
                    mma_bf16(O[n], ph[kc], bl0, bl1);
                    mma_bf16(O[n], pl[kc], bh0, bh1);
                }
            }
        }

        // ---- epilogue for this item ----
        float inv0 = 1.0f / ls0, inv1 = 1.0f / ls1;
        float* o0 = out + ((size_t)(nb * LL + row0) * HH + h) * EE;
        float* o1 = o0 + 8 * HH * EE;
        #pragma unroll
        for (int n = 0; n < 8; n++) {
            int e = n * 8 + 2 * t;
            *(float2*)(o0 + e) = make_float2(O[n][0] * inv0, O[n][1] * inv0);
            *(float2*)(o1 + e) = make_float2(O[n][2] * inv1, O[n][3] * inv1);
        }

        // ---- next work item ----
        __shared__ unsigned s_item;
        __syncthreads();
        if (tid == 0) s_item = atomicAdd(&g_ctr, 1u);
        __syncthreads();
        item = s_item;
    }
}

// ---------------------------------------------------------------------------
extern "C" void kernel_launch(void* const* d_in, const int* in_sizes, int n_in,
                              void* d_out, int out_size) {
    const float* queries = (const float*)d_in[0];
    const float* keys    = (const float*)d_in[1];
    const float* values  = (const float*)d_in[2];
    const float* mask    = (const float*)d_in[3];
    const float* keylen  = (const float*)d_in[4];
    const float* freqs   = (const float*)d_in[5];
    const float* offsets = (const float*)d_in[6];
    const float* gains   = (const float*)d_in[7];
    const float* gate    = (const float*)d_in[8];
    float* out = (float*)d_out;

    prep_kernel<<<dim3(48 + NTILE, NH), 256>>>(queries, keys, values,
                                               freqs, offsets, gains, gate);

    const int smem = (2 * 64 * KSTR + 4 * 64 * VSTR) * 2;   // 88064 B
    cudaFuncSetAttribute(attn_kernel, cudaFuncAttributeMaxDynamicSharedMemorySize, smem);
    attn_kernel<<<GRID_ATTN, 128, smem>>>(mask, keylen, out);
}

// round 8
// speedup vs baseline: 1.3084x; 1.0114x over previous
#include <cuda_runtime.h>
#include <cuda_bf16.h>
#include <math_constants.h>
#include <cstdint>

#define LL 768
#define HH 8
#define EE 64
#define NH 32
#define DD 192
#define BQ 64
#define NTILE 12
#define NITEMS 384          // 12 l-tiles x 32 nh
#define GRID_ATTN 304
#define KSTR 200            // padded smem row stride (bf16)
#define VSTR 72

// ---------------- scratch (device globals; no allocs) ----------------
// d-layout: d = e for gate channel (0..63); d = 64+2e (cos), 65+2e (sin).
__device__ __nv_bfloat16 g_Qhi[(size_t)NH * LL * DD];
__device__ __nv_bfloat16 g_Qlo[(size_t)NH * LL * DD];
__device__ __nv_bfloat16 g_Khi[(size_t)NH * LL * DD];
__device__ __nv_bfloat16 g_Klo[(size_t)NH * LL * DD];
__device__ __nv_bfloat16 g_Vhi[(size_t)NH * EE * LL];   // transposed [nh][e][s]
__device__ __nv_bfloat16 g_Vlo[(size_t)NH * EE * LL];
__device__ unsigned int  g_ctr;

// m16n8k16 row.col bf16 MMA, f32 accumulate
__device__ __forceinline__ void mma_bf16(float* c, const uint32_t* a, uint32_t b0, uint32_t b1) {
    asm volatile("mma.sync.aligned.m16n8k16.row.col.f32.bf16.bf16.f32 "
                 "{%0,%1,%2,%3}, {%4,%5,%6,%7}, {%8,%9}, {%0,%1,%2,%3};"
                 : "+f"(c[0]), "+f"(c[1]), "+f"(c[2]), "+f"(c[3])
                 : "r"(a[0]), "r"(a[1]), "r"(a[2]), "r"(a[3]), "r"(b0), "r"(b1));
}

__device__ __forceinline__ uint32_t smem_u32(const void* p) {
    uint32_t a;
    asm("{ .reg .u64 t; cvta.to.shared.u64 t, %1; cvt.u32.u64 %0, t; }" : "=r"(a) : "l"(p));
    return a;
}

#define CP16(dst, src) asm volatile("cp.async.cg.shared.global [%0], [%1], 16;" :: "r"(dst), "l"(src))
#define CP_COMMIT()    asm volatile("cp.async.commit_group;" ::: "memory")
#define CP_WAIT0()     asm volatile("cp.async.wait_group 0;" ::: "memory")

__device__ __forceinline__ uint32_t pack_hi(float x, float y, uint32_t& lo) {
    __nv_bfloat162 h2;
    h2.x = __float2bfloat16(x);
    h2.y = __float2bfloat16(y);
    __nv_bfloat162 l2;
    l2.x = __float2bfloat16(x - __bfloat162float(h2.x));
    l2.y = __float2bfloat16(y - __bfloat162float(h2.y));
    lo = *(uint32_t*)&l2;
    return *(uint32_t*)&h2;
}

// ---------------------------------------------------------------------------
// prep (fused): blockIdx.x < 48 -> Q'/K' build; else -> V transpose.
// ---------------------------------------------------------------------------
__global__ void prep_kernel(const float* __restrict__ q, const float* __restrict__ k,
                            const float* __restrict__ values,
                            const float* __restrict__ freqs, const float* __restrict__ offsets,
                            const float* __restrict__ gains, const float* __restrict__ gate) {
    const int nh = blockIdx.y;
    const int n = nh >> 3, h = nh & 7;

    if (blockIdx.x < 48) {
        if (blockIdx.x == 0 && blockIdx.y == 0 && threadIdx.x == 0)
            g_ctr = GRID_ATTN;                // seed attn work queue

        int e  = threadIdx.x & 63;
        int j  = threadIdx.x >> 6;            // 0..3
        int l0 = blockIdx.x * 16 + j * 4;
        int he = h * 64 + e;

        float fr  = freqs[he];
        float f   = 0.5f / (1.0f + __expf(-fr));
        float off = offsets[he];
        float gn  = gains[he];
        float g   = (gn > 8.0f) ? gn : __logf(1.0f + __expf(gn));
        float gt  = gate[he];
        float c   = (1.0f - gt) * g * g;

        float lf    = (float)l0;
        float fl    = f * lf;
        float resid = fmaf(f, lf, -fl);
        float frac  = (fl - floorf(fl)) + resid;
        const float TWO_PI = 6.28318530717958647692f;
        float phk   = TWO_PI * frac;
        float argq  = phk + off;
        float cq = __cosf(argq), sq = __sinf(argq);
        float ck = __cosf(phk),  sk = __sinf(phk);
        float dph = TWO_PI * f;
        float cF = __cosf(dph), sF = __sinf(dph);

        #pragma unroll
        for (int dl = 0; dl < 4; dl++) {
            int l = l0 + dl;
            size_t qi = ((size_t)(n * LL + l) * HH + h) * EE + e;
            float qv = q[qi] * 0.125f;        // softmax temp folded into Q'
            float kv = k[qi];

            size_t base = ((size_t)nh * LL + l) * DD;
            {
                float v = qv * gt;
                __nv_bfloat16 hi = __float2bfloat16(v);
                g_Qhi[base + e] = hi;
                g_Qlo[base + e] = __float2bfloat16(v - __bfloat162float(hi));
                __nv_bfloat16 whi = __float2bfloat16(kv);
                g_Khi[base + e] = whi;
                g_Klo[base + e] = __float2bfloat16(kv - __bfloat162float(whi));
            }
            {
                float qc = qv * c;
                float vx = qc * cq, vy = qc * sq;
                uint32_t lo;
                uint32_t hi = pack_hi(vx, vy, lo);
                *(uint32_t*)(g_Qhi + base + 64 + 2 * e) = hi;
                *(uint32_t*)(g_Qlo + base + 64 + 2 * e) = lo;
                float wx = kv * ck, wy = kv * sk;
                uint32_t wlo;
                uint32_t whi = pack_hi(wx, wy, wlo);
                *(uint32_t*)(g_Khi + base + 64 + 2 * e) = whi;
                *(uint32_t*)(g_Klo + base + 64 + 2 * e) = wlo;
            }
            float cq2 = cq * cF - sq * sF, sq2 = sq * cF + cq * sF;
            float ck2 = ck * cF - sk * sF, sk2 = sk * cF + ck * sF;
            cq = cq2; sq = sq2; ck = ck2; sk = sk2;
        }
    } else {
        __shared__ float sm[64 * 65];
        int t = blockIdx.x - 48;
        int s0 = t * 64;

        #pragma unroll
        for (int i = 0; i < 16; i++) {
            int idx = threadIdx.x + i * 256;
            int r = idx >> 6, e = idx & 63;
            sm[e * 65 + r] = values[((size_t)(n * LL + s0 + r) * HH + h) * EE + e];
        }
        __syncthreads();

        #pragma unroll
        for (int i = 0; i < 8; i++) {
            int pid = threadIdx.x + i * 256;
            int e = pid >> 5, s2 = pid & 31;
            float v0 = sm[e * 65 + 2 * s2];
            float v1 = sm[e * 65 + 2 * s2 + 1];
            uint32_t lo;
            uint32_t hi = pack_hi(v0, v1, lo);
            size_t o = ((size_t)nh * EE + e) * LL + s0 + 2 * s2;
            *(uint32_t*)(g_Vhi + o) = hi;
            *(uint32_t*)(g_Vlo + o) = lo;
        }
    }
}

// ---------------------------------------------------------------------------
// attn: persistent work-queue flash attention on HMMA (bf16 3-product),
// cp.async pipelined. MMAs issued product-major / n-minor so consecutive
// instructions hit different accumulators (breaks RAW chains).
// ---------------------------------------------------------------------------
__global__ __launch_bounds__(128)
void attn_kernel(const float* __restrict__ mask, const float* __restrict__ keylen,
                 float* __restrict__ out) {
    extern __shared__ __nv_bfloat16 smem[];
    __nv_bfloat16* sKhi = smem;                              // [64][KSTR]
    __nv_bfloat16* sKlo = smem + 64 * KSTR;
    __nv_bfloat16* sVhi = smem + 2 * 64 * KSTR;              // [2][64][VSTR]
    __nv_bfloat16* sVlo = smem + 2 * 64 * KSTR + 2 * 64 * VSTR;

    const int tid  = threadIdx.x;
    const int w    = tid >> 5;
    const int lane = tid & 31;
    const int g    = lane >> 2, t = lane & 3;

    const uint32_t bKhi = smem_u32(sKhi);
    const uint32_t bKlo = smem_u32(sKlo);
    const uint32_t bVhi = smem_u32(sVhi);
    const uint32_t bVlo = smem_u32(sVlo);

    unsigned item = blockIdx.x;
    while (item < NITEMS) {
        const int nh = (int)(item / NTILE);
        const int lt = (int)(item % NTILE);
        const int nb = nh >> 3, h = nh & 7;
        const int l0 = lt * BQ;
        const int row0 = l0 + w * 16 + g;

        const uint4* gKhiB = (const uint4*)(g_Khi + (size_t)nh * LL * DD);
        const uint4* gKloB = (const uint4*)(g_Klo + (size_t)nh * LL * DD);

        auto issue_tile = [&](int it2, int vb) {
            const uint4* gH = gKhiB + (size_t)it2 * 64 * DD / 8;
            const uint4* gL = gKloB + (size_t)it2 * 64 * DD / 8;
            #pragma unroll
            for (int i = 0; i < 12; i++) {
                int idx = tid + i * 128;
                int r = idx / 24, c = idx % 24;
                uint32_t off = (uint32_t)(r * KSTR + c * 8) * 2u;
                CP16(bKhi + off, gH + idx);
                CP16(bKlo + off, gL + idx);
            }
            #pragma unroll
            for (int i = 0; i < 4; i++) {
                int idx = tid + i * 128;
                int r = idx / 8, c = idx % 8;
                size_t go = ((size_t)nh * EE + r) * LL + it2 * 64 + c * 8;
                uint32_t off = (uint32_t)(vb * 64 * VSTR + r * VSTR + c * 8) * 2u;
                CP16(bVhi + off, (const uint4*)(g_Vhi + go));
                CP16(bVlo + off, (const uint4*)(g_Vlo + go));
            }
        };

        issue_tile(0, 0);
        CP_COMMIT();

        // ---- Q fragments (register resident for this item) ----
        uint32_t aQh[12][4], aQl[12][4];
        {
            const __nv_bfloat16* qh = g_Qhi + ((size_t)nh * LL + row0) * DD;
            const __nv_bfloat16* ql = g_Qlo + ((size_t)nh * LL + row0) * DD;
            #pragma unroll
            for (int c = 0; c < 12; c++) {
                int d0 = c * 16 + 2 * t;
                aQh[c][0] = *(const uint32_t*)(qh + d0);
                aQh[c][1] = *(const uint32_t*)(qh + 8 * DD + d0);
                aQh[c][2] = *(const uint32_t*)(qh + d0 + 8);
                aQh[c][3] = *(const uint32_t*)(qh + 8 * DD + d0 + 8);
                aQl[c][0] = *(const uint32_t*)(ql + d0);
                aQl[c][1] = *(const uint32_t*)(ql + 8 * DD + d0);
                aQl[c][2] = *(const uint32_t*)(ql + d0 + 8);
                aQl[c][3] = *(const uint32_t*)(ql + 8 * DD + d0 + 8);
            }
        }

        float O[8][4];
        #pragma unroll
        for (int n = 0; n < 8; n++)
            #pragma unroll
            for (int j = 0; j < 4; j++) O[n][j] = 0.f;
        float m0 = -CUDART_INF_F, m1 = -CUDART_INF_F, ls0 = 0.f, ls1 = 0.f;

        const float* mrow0b = mask + (size_t)row0 * LL;
        const float* mrow1b = mrow0b + 8 * LL;
        const float* klb    = keylen + (size_t)nb * LL;

        for (int it = 0; it < NTILE; it++) {
            CP_WAIT0();
            __syncthreads();

            // ---- S = Q' K'^T : c outer, B frags staged, n-minor MMA issue ----
            float S[8][4];
            #pragma unroll
            for (int n = 0; n < 8; n++)
                #pragma unroll
                for (int j = 0; j < 4; j++) S[n][j] = 0.f;

            #pragma unroll
            for (int c = 0; c < 12; c++) {
                uint32_t bh[8][2], bl[8][2];
                #pragma unroll
                for (int n = 0; n < 8; n++) {
                    const __nv_bfloat16* kh = sKhi + (n * 8 + g) * KSTR + 2 * t + c * 16;
                    const __nv_bfloat16* kl = sKlo + (n * 8 + g) * KSTR + 2 * t + c * 16;
                    bh[n][0] = *(const uint32_t*)(kh);
                    bh[n][1] = *(const uint32_t*)(kh + 8);
                    bl[n][0] = *(const uint32_t*)(kl);
                    bl[n][1] = *(const uint32_t*)(kl + 8);
                }
                #pragma unroll
                for (int n = 0; n < 8; n++) mma_bf16(S[n], aQh[c], bh[n][0], bh[n][1]);
                #pragma unroll
                for (int n = 0; n < 8; n++) mma_bf16(S[n], aQh[c], bl[n][0], bl[n][1]);
                #pragma unroll
                for (int n = 0; n < 8; n++) mma_bf16(S[n], aQl[c], bh[n][0], bh[n][1]);
            }
            __syncthreads();   // all warps done reading K smem

            if (it + 1 < NTILE) { issue_tile(it + 1, (it + 1) & 1); }
            CP_COMMIT();

            // ---- bias: 0.125 * (mask + keylen) ----
            {
                const float* mr0 = mrow0b + it * 64;
                const float* mr1 = mrow1b + it * 64;
                const float* kl  = klb + it * 64;
                #pragma unroll
                for (int n = 0; n < 8; n++) {
                    int sc = n * 8 + 2 * t;
                    float2 a0 = *(const float2*)(mr0 + sc);
                    float2 a1 = *(const float2*)(mr1 + sc);
                    float2 kk = *(const float2*)(kl + sc);
                    S[n][0] += 0.125f * (a0.x + kk.x);
                    S[n][1] += 0.125f * (a0.y + kk.y);
                    S[n][2] += 0.125f * (a1.x + kk.x);
                    S[n][3] += 0.125f * (a1.y + kk.y);
                }
            }

            // ---- online softmax (rows quad-local) ----
            float mx0 = S[0][0], mx1 = S[0][2];
            #pragma unroll
            for (int n = 0; n < 8; n++) {
                mx0 = fmaxf(mx0, fmaxf(S[n][0], S[n][1]));
                mx1 = fmaxf(mx1, fmaxf(S[n][2], S[n][3]));
            }
            mx0 = fmaxf(mx0, __shfl_xor_sync(0xffffffffu, mx0, 1));
            mx0 = fmaxf(mx0, __shfl_xor_sync(0xffffffffu, mx0, 2));
            mx1 = fmaxf(mx1, __shfl_xor_sync(0xffffffffu, mx1, 1));
            mx1 = fmaxf(mx1, __shfl_xor_sync(0xffffffffu, mx1, 2));
            float m0n = fmaxf(m0, mx0), m1n = fmaxf(m1, mx1);
            float c0 = __expf(m0 - m0n), c1 = __expf(m1 - m1n);
            m0 = m0n; m1 = m1n;
            float s0 = 0.f, s1 = 0.f;
            #pragma unroll
            for (int n = 0; n < 8; n++) {
                S[n][0] = __expf(S[n][0] - m0n);
                S[n][1] = __expf(S[n][1] - m0n);
                S[n][2] = __expf(S[n][2] - m1n);
                S[n][3] = __expf(S[n][3] - m1n);
                s0 += S[n][0] + S[n][1];
                s1 += S[n][2] + S[n][3];
                O[n][0] *= c0; O[n][1] *= c0;
                O[n][2] *= c1; O[n][3] *= c1;
            }
            s0 += __shfl_xor_sync(0xffffffffu, s0, 1);
            s0 += __shfl_xor_sync(0xffffffffu, s0, 2);
            s1 += __shfl_xor_sync(0xffffffffu, s1, 1);
            s1 += __shfl_xor_sync(0xffffffffu, s1, 2);
            ls0 = ls0 * c0 + s0;
            ls1 = ls1 * c1 + s1;

            // ---- P -> bf16 hi/lo A-fragments (in-register) ----
            uint32_t ph[4][4], pl[4][4];
            #pragma unroll
            for (int kc = 0; kc < 4; kc++) {
                ph[kc][0] = pack_hi(S[2*kc][0],   S[2*kc][1],   pl[kc][0]);
                ph[kc][1] = pack_hi(S[2*kc][2],   S[2*kc][3],   pl[kc][1]);
                ph[kc][2] = pack_hi(S[2*kc+1][0], S[2*kc+1][1], pl[kc][2]);
                ph[kc][3] = pack_hi(S[2*kc+1][2], S[2*kc+1][3], pl[kc][3]);
            }

            // ---- O += P V : kc outer, staged V frags, n-minor MMA issue ----
            const __nv_bfloat16* vbH = sVhi + (it & 1) * 64 * VSTR;
            const __nv_bfloat16* vbL = sVlo + (it & 1) * 64 * VSTR;
            #pragma unroll
            for (int kc = 0; kc < 4; kc++) {
                uint32_t vh[8][2], vl[8][2];
                #pragma unroll
                for (int n = 0; n < 8; n++) {
                    const __nv_bfloat16* vhp = vbH + (n * 8 + g) * VSTR + 2 * t + kc * 16;
                    const __nv_bfloat16* vlp = vbL + (n * 8 + g) * VSTR + 2 * t + kc * 16;
                    vh[n][0] = *(const uint32_t*)(vhp);
                    vh[n][1] = *(const uint32_t*)(vhp + 8);
                    vl[n][0] = *(const uint32_t*)(vlp);
                    vl[n][1] = *(const uint32_t*)(vlp + 8);
                }
                #pragma unroll
                for (int n = 0; n < 8; n++) mma_bf16(O[n], ph[kc], vh[n][0], vh[n][1]);
                #pragma unroll
                for (int n = 0; n < 8; n++) mma_bf16(O[n], ph[kc], vl[n][0], vl[n][1]);
                #pragma unroll
                for (int n = 0; n < 8; n++) mma_bf16(O[n], pl[kc], vh[n][0], vh[n][1]);
            }
        }

        // ---- epilogue for this item ----
        float inv0 = 1.0f / ls0, inv1 = 1.0f / ls1;
        float* o0 = out + ((size_t)(nb * LL + row0) * HH + h) * EE;
        float* o1 = o0 + 8 * HH * EE;
        #pragma unroll
        for (int n = 0; n < 8; n++) {
            int e = n * 8 + 2 * t;
            *(float2*)(o0 + e) = make_float2(O[n][0] * inv0, O[n][1] * inv0);
            *(float2*)(o1 + e) = make_float2(O[n][2] * inv1, O[n][3] * inv1);
        }

        // ---- next work item ----
        __shared__ unsigned s_item;
        __syncthreads();
        if (tid == 0) s_item = atomicAdd(&g_ctr, 1u);
        __syncthreads();
        item = s_item;
    }
}

// ---------------------------------------------------------------------------
extern "C" void kernel_launch(void* const* d_in, const int* in_sizes, int n_in,
                              void* d_out, int out_size) {
    const float* queries = (const float*)d_in[0];
    const float* keys    = (const float*)d_in[1];
    const float* values  = (const float*)d_in[2];
    const float* mask    = (const float*)d_in[3];
    const float* keylen  = (const float*)d_in[4];
    const float* freqs   = (const float*)d_in[5];
    const float* offsets = (const float*)d_in[6];
    const float* gains   = (const float*)d_in[7];
    const float* gate    = (const float*)d_in[8];
    float* out = (float*)d_out;

    prep_kernel<<<dim3(48 + NTILE, NH), 256>>>(queries, keys, values,
                                               freqs, offsets, gains, gate);

    const int smem = (2 * 64 * KSTR + 4 * 64 * VSTR) * 2;   // 88064 B
    cudaFuncSetAttribute(attn_kernel, cudaFuncAttributeMaxDynamicSharedMemorySize, smem);
    attn_kernel<<<GRID_ATTN, 128, smem>>>(mask, keylen, out);
}